// round 12
// baseline (speedup 1.0000x reference)
#include <cuda_runtime.h>

#define BB 4
#define DD 128
#define KK 512
// e = C1*(sL+sR) + C2*sum|t|a + bias, with alpha=0.2
#define C1 0.6f
#define C2 0.4f

typedef unsigned long long ull;
#define ABSM 0x7FFFFFFF7FFFFFFFULL

__device__ __forceinline__ ull uadd2(ull a, ull b) {
    ull r; asm("add.rn.f32x2 %0,%1,%2;" : "=l"(r) : "l"(a), "l"(b)); return r;
}
__device__ __forceinline__ ull ufma2(ull a, ull b, ull c) {
    ull r; asm("fma.rn.f32x2 %0,%1,%2,%3;" : "=l"(r) : "l"(a), "l"(b), "l"(c)); return r;
}
__device__ __forceinline__ ull bc2(float x) {
    ull r; asm("mov.b64 %0,{%1,%1};" : "=l"(r) : "f"(x)); return r;
}
__device__ __forceinline__ ull pk2(float x, float y) {
    ull r; asm("mov.b64 %0,{%1,%2};" : "=l"(r) : "f"(x), "f"(y)); return r;
}
__device__ __forceinline__ float2 up2(ull v) {
    float2 f; asm("mov.b64 {%0,%1},%2;" : "=f"(f.x), "=f"(f.y) : "l"(v)); return f;
}

__device__ float g_R[BB * DD * KK];   // [b][e][k]  (d-major)
__device__ float g_XT[BB * KK * DD];  // [b][k][d]
__device__ float g_sR[BB * KK];

// grid barrier state (zero-init)
__device__ unsigned int g_barc;
__device__ volatile unsigned int g_gen;

// smem floats: sLd[128][8] dup @0 (2048) | sAd[128] dup @2048 (256)
//              part[2][8][512] @2304 (8192) | se[8][512] @10496 (4096)
#define OF_SAD  2048
#define OF_PART 2304
#define OF_SE   10496
#define SM_FLTS 14592

__global__ __launch_bounds__(256, 3) void kfused(const float* __restrict__ x,
                                                 const float* __restrict__ lw,
                                                 const float* __restrict__ lb,
                                                 const float* __restrict__ a,
                                                 const float* __restrict__ bias,
                                                 float* __restrict__ out) {
    extern __shared__ float sm[];
    ull*   sLd  = (ull*)sm;            // [d][i] dup pairs
    ull*   sAd  = (ull*)(sm + OF_SAD); // [d] dup pairs
    float* part = sm + OF_PART;        // [sp][i][j]  (phase A: sx area)
    float* se   = sm + OF_SE;          // [i][j]
    __shared__ float sSL[8], ssR[8];

    const int tid = threadIdx.x;
    const int b = blockIdx.x >> 6;
    const int i0 = (blockIdx.x & 63) << 3;
    const int nblk = gridDim.x;

    // ================= Phase A: compute L (smem), R/XT/sR (global) =========
    float* sx = part;  // [d][k] pad 9
    for (int idx = tid; idx < 1024; idx += 256) {
        int d = idx >> 3, kk = idx & 7;
        sx[d * 9 + kk] = x[(b * DD + d) * KK + i0 + kk];
    }
    if (tid < 8) { sSL[tid] = 0.f; ssR[tid] = 0.f; }
    if (tid < 128) sAd[tid] = bc2(a[tid]);
    __syncthreads();

    {
        const int k = tid & 7;
        const int o8 = tid >> 3;
        const int isL = (o8 < 16);
        const int e0 = (o8 & 15) * 8;
        const float* Wb = lw + (isL ? 0 : 128 * 128) + e0;

        float acc[8] = {0, 0, 0, 0, 0, 0, 0, 0};
#pragma unroll 4
        for (int d = 0; d < 128; d++) {
            float xv = sx[d * 9 + k];
            float4 w0 = *(const float4*)(Wb + d * 128);
            float4 w1 = *(const float4*)(Wb + d * 128 + 4);
            acc[0] = fmaf(xv, w0.x, acc[0]); acc[1] = fmaf(xv, w0.y, acc[1]);
            acc[2] = fmaf(xv, w0.z, acc[2]); acc[3] = fmaf(xv, w0.w, acc[3]);
            acc[4] = fmaf(xv, w1.x, acc[4]); acc[5] = fmaf(xv, w1.y, acc[5]);
            acc[6] = fmaf(xv, w1.z, acc[6]); acc[7] = fmaf(xv, w1.w, acc[7]);
        }

        const float4 a0 = *(const float4*)&a[e0];
        const float4 a1 = *(const float4*)&a[e0 + 4];
        if (isL) {
            const float4 b0 = *(const float4*)&lb[e0];
            const float4 b1 = *(const float4*)&lb[e0 + 4];
            acc[0] += b0.x; acc[1] += b0.y; acc[2] += b0.z; acc[3] += b0.w;
            acc[4] += b1.x; acc[5] += b1.y; acc[6] += b1.z; acc[7] += b1.w;
#pragma unroll
            for (int q = 0; q < 8; q++) sLd[(e0 + q) * 8 + k] = bc2(acc[q]);
        } else {
#pragma unroll
            for (int q = 0; q < 8; q++)
                g_R[(b * DD + e0 + q) * KK + i0 + k] = acc[q];
        }
        float p = acc[0] * a0.x + acc[1] * a0.y + acc[2] * a0.z + acc[3] * a0.w +
                  acc[4] * a1.x + acc[5] * a1.y + acc[6] * a1.z + acc[7] * a1.w;
        atomicAdd(isL ? &sSL[k] : &ssR[k], p);
    }
    __syncthreads();

    for (int idx = tid; idx < 1024; idx += 256) {
        int kk = idx >> 7, d = idx & 127;
        g_XT[(b * KK + i0 + kk) * DD + d] = sx[d * 9 + kk];
    }
    if (tid < 8) g_sR[b * KK + i0 + tid] = ssR[tid];
    __syncthreads();

    // ================= grid barrier (all 256 CTAs resident) ================
    if (tid == 0) {
        __threadfence();
        unsigned my_gen = g_gen;
        unsigned arrived = atomicAdd(&g_barc, 1u);
        if (arrived == (unsigned)nblk - 1u) {
            g_barc = 0u;
            __threadfence();
            g_gen = my_gen + 1u;
        } else {
            while (g_gen == my_gen) __nanosleep(40);
        }
        __threadfence();
    }
    __syncthreads();

    // ================= Phase B ============================================
    // ---- e phase: split-d (sp), thread = 4 j (2 packed j-pairs) x 8 i ----
    {
        const int jq = tid & 127;
        const int sp = tid >> 7;
        const float* Rb = g_R + (b * DD + sp * 64) * KK + jq * 4;
        const ull* sLdsp = sLd + sp * 64 * 8;
        const ull* sAdsp = sAd + sp * 64;
        ull acc[8][2];
#pragma unroll
        for (int i = 0; i < 8; i++) { acc[i][0] = 0ull; acc[i][1] = 0ull; }

#pragma unroll 4
        for (int dd = 0; dd < 64; dd++) {
            float4 rq = *(const float4*)(Rb + dd * KK);
            ull r01 = pk2(rq.x, rq.y), r23 = pk2(rq.z, rq.w);
            ull av2 = sAdsp[dd];
#pragma unroll
            for (int i = 0; i < 8; i++) {
                ull l2 = sLdsp[dd * 8 + i];
                ull u0 = uadd2(l2, r01) & ABSM;
                ull u1 = uadd2(l2, r23) & ABSM;
                acc[i][0] = ufma2(u0, av2, acc[i][0]);
                acc[i][1] = ufma2(u1, av2, acc[i][1]);
            }
        }
        float* pp = part + sp * 4096 + jq * 4;
#pragma unroll
        for (int i = 0; i < 8; i++) {
            float2 q0 = up2(acc[i][0]), q1 = up2(acc[i][1]);
            *(float4*)&pp[i * KK] = make_float4(q0.x, q0.y, q1.x, q1.y);
        }
    }
    __syncthreads();

    // ---- combine: e = C1*(sL+sR) + C2*(p0+p1) + bias -> se[i][j] ----
    {
        const int jq2 = tid & 127;
        const int ih0 = (tid >> 7) * 4;
        float4 sr = *(const float4*)&g_sR[b * KK + jq2 * 4];
#pragma unroll
        for (int r = 0; r < 4; r++) {
            int i = ih0 + r;
            float4 p0 = *(const float4*)&part[i * KK + jq2 * 4];
            float4 p1 = *(const float4*)&part[4096 + i * KK + jq2 * 4];
            float4 bz = *(const float4*)&bias[(long)(i0 + i) * KK + jq2 * 4];
            float sl = sSL[i];
            float4 ev;
            ev.x = C1 * (sl + sr.x) + C2 * (p0.x + p1.x) + bz.x;
            ev.y = C1 * (sl + sr.y) + C2 * (p0.y + p1.y) + bz.y;
            ev.z = C1 * (sl + sr.z) + C2 * (p0.z + p1.z) + bz.z;
            ev.w = C1 * (sl + sr.w) + C2 * (p0.w + p1.w) + bz.w;
            *(float4*)&se[i * KK + jq2 * 4] = ev;
        }
    }
    __syncthreads();

    // ---- softmax: warp w -> row i=w ----
    {
        const int w = tid >> 5, lane = tid & 31;
        float* row = se + w * KK;
        float v[16], m = -3.4e38f;
#pragma unroll
        for (int t = 0; t < 16; t++) { v[t] = row[t * 32 + lane]; m = fmaxf(m, v[t]); }
#pragma unroll
        for (int o = 16; o > 0; o >>= 1) m = fmaxf(m, __shfl_xor_sync(0xffffffffu, m, o));
        float s = 0.f;
#pragma unroll
        for (int t = 0; t < 16; t++) { v[t] = __expf(v[t] - m); s += v[t]; }
#pragma unroll
        for (int o = 16; o > 0; o >>= 1) s += __shfl_xor_sync(0xffffffffu, s, o);
        float inv = 1.f / s;
#pragma unroll
        for (int t = 0; t < 16; t++) row[t * 32 + lane] = v[t] * inv;
    }
    __syncthreads();

    // ---- agg: attn @ XT, thread = (j-slice, d-quad), d packed in pairs ----
    const int d4 = tid & 31;
    const int js = tid >> 5;
    {
        const float* Xb = g_XT + (b * KK + js * 64) * DD + d4 * 4;
        ull ag[8][2];
#pragma unroll
        for (int i = 0; i < 8; i++) { ag[i][0] = 0ull; ag[i][1] = 0ull; }

#pragma unroll 4
        for (int t = 0; t < 64; t++) {
            float4 xq = *(const float4*)(Xb + t * DD);
            ull x01 = pk2(xq.x, xq.y), x23 = pk2(xq.z, xq.w);
            const int j = js * 64 + t;
#pragma unroll
            for (int i = 0; i < 8; i++) {
                ull a2 = bc2(se[i * KK + j]);
                ag[i][0] = ufma2(a2, x01, ag[i][0]);
                ag[i][1] = ufma2(a2, x23, ag[i][1]);
            }
        }
        float* red = part;  // [js][i][d]
#pragma unroll
        for (int i = 0; i < 8; i++) {
            float2 q0 = up2(ag[i][0]), q1 = up2(ag[i][1]);
            *(float4*)&red[js * 1024 + i * 128 + d4 * 4] =
                make_float4(q0.x, q0.y, q1.x, q1.y);
        }
    }
    __syncthreads();

    // ---- reduce over j-slices + sigmoid + residual ----
    {
        const float* red = part;
        const int i2 = tid >> 5;
        const int dq = (tid & 31) * 4;
        float4 s = make_float4(0.f, 0.f, 0.f, 0.f);
#pragma unroll
        for (int r = 0; r < 8; r++) {
            float4 p = *(const float4*)&red[r * 1024 + i2 * 128 + dq];
            s.x += p.x; s.y += p.y; s.z += p.z; s.w += p.w;
        }
        float4 xt = *(const float4*)&g_XT[(b * KK + i0 + i2) * DD + dq];
        out[(b * DD + dq + 0) * KK + i0 + i2] = 1.f / (1.f + __expf(-s.x)) + xt.x;
        out[(b * DD + dq + 1) * KK + i0 + i2] = 1.f / (1.f + __expf(-s.y)) + xt.y;
        out[(b * DD + dq + 2) * KK + i0 + i2] = 1.f / (1.f + __expf(-s.z)) + xt.z;
        out[(b * DD + dq + 3) * KK + i0 + i2] = 1.f / (1.f + __expf(-s.w)) + xt.w;
    }
}

extern "C" void kernel_launch(void* const* d_in, const int* in_sizes, int n_in,
                              void* d_out, int out_size) {
    const float* x    = (const float*)d_in[0];
    const float* lw   = (const float*)d_in[1];
    const float* lb   = (const float*)d_in[2];
    const float* a    = (const float*)d_in[3];
    const float* bias = (const float*)d_in[4];
    float* out = (float*)d_out;

    static bool attr_set = false;
    if (!attr_set) {
        cudaFuncSetAttribute(kfused, cudaFuncAttributeMaxDynamicSharedMemorySize,
                             SM_FLTS * 4);
        attr_set = true;
    }
    kfused<<<256, 256, SM_FLTS * 4>>>(x, lw, lb, a, bias, out);
}

// round 13
// speedup vs baseline: 1.0539x; 1.0539x over previous
#include <cuda_runtime.h>

#define BB 4
#define DD 128
#define KK 512
// e = C1*(sL+sR) + C2*sum|t|a + bias, with alpha=0.2
#define C1 0.6f
#define C2 0.4f

typedef unsigned long long ull;
#define ABSM 0x7FFFFFFF7FFFFFFFULL

__device__ __forceinline__ ull uadd2(ull a, ull b) {
    ull r; asm("add.rn.f32x2 %0,%1,%2;" : "=l"(r) : "l"(a), "l"(b)); return r;
}
__device__ __forceinline__ ull ufma2(ull a, ull b, ull c) {
    ull r; asm("fma.rn.f32x2 %0,%1,%2,%3;" : "=l"(r) : "l"(a), "l"(b), "l"(c)); return r;
}
__device__ __forceinline__ ull bc2(float x) {
    ull r; asm("mov.b64 %0,{%1,%1};" : "=l"(r) : "f"(x)); return r;
}
__device__ __forceinline__ ull pk2(float x, float y) {
    ull r; asm("mov.b64 %0,{%1,%2};" : "=l"(r) : "f"(x), "f"(y)); return r;
}
__device__ __forceinline__ float2 up2(ull v) {
    float2 f; asm("mov.b64 {%0,%1},%2;" : "=f"(f.x), "=f"(f.y) : "l"(v)); return f;
}

__device__ float g_R[BB * DD * KK];   // [b][e][k]  (d-major)
__device__ float g_XT[BB * KK * DD];  // [b][k][d]
__device__ float g_sR[BB * KK];

// grid barrier state (zero-init)
__device__ unsigned int g_barc;
__device__ volatile unsigned int g_gen;

// smem floats: sLd[128][8] dup @0 (2048) | sAd[128] dup @2048 (256)
//              part[2][8][512] @2304 (8192) | seU[8][512] ull dup @10496 (8192)
#define OF_SAD  2048
#define OF_PART 2304
#define OF_SE   10496
#define SM_FLTS 18688

__global__ __launch_bounds__(256, 2) void kfused(const float* __restrict__ x,
                                                 const float* __restrict__ lw,
                                                 const float* __restrict__ lb,
                                                 const float* __restrict__ a,
                                                 const float* __restrict__ bias,
                                                 float* __restrict__ out) {
    extern __shared__ float sm[];
    ull*   sLd  = (ull*)sm;            // [d][i] dup pairs
    ull*   sAd  = (ull*)(sm + OF_SAD); // [d] dup pairs
    float* part = sm + OF_PART;        // [sp][i][j]  (phase A: sx area)
    ull*   seU  = (ull*)(sm + OF_SE);  // [i][j] attn, duplicated pairs
    __shared__ float sSL[8], ssR[8];

    const int tid = threadIdx.x;
    const int b = blockIdx.x >> 6;
    const int i0 = (blockIdx.x & 63) << 3;
    const int nblk = gridDim.x;

    // ================= Phase A: compute L (smem), R/XT/sR (global) =========
    float* sx = part;  // [d][k] pad 9
    for (int idx = tid; idx < 1024; idx += 256) {
        int d = idx >> 3, kk = idx & 7;
        sx[d * 9 + kk] = x[(b * DD + d) * KK + i0 + kk];
    }
    if (tid < 8) { sSL[tid] = 0.f; ssR[tid] = 0.f; }
    if (tid < 128) sAd[tid] = bc2(a[tid]);
    __syncthreads();

    {
        const int k = tid & 7;
        const int o8 = tid >> 3;
        const int isL = (o8 < 16);
        const int e0 = (o8 & 15) * 8;
        const float* Wb = lw + (isL ? 0 : 128 * 128) + e0;

        float acc[8] = {0, 0, 0, 0, 0, 0, 0, 0};
#pragma unroll 8
        for (int d = 0; d < 128; d++) {
            float xv = sx[d * 9 + k];
            float4 w0 = *(const float4*)(Wb + d * 128);
            float4 w1 = *(const float4*)(Wb + d * 128 + 4);
            acc[0] = fmaf(xv, w0.x, acc[0]); acc[1] = fmaf(xv, w0.y, acc[1]);
            acc[2] = fmaf(xv, w0.z, acc[2]); acc[3] = fmaf(xv, w0.w, acc[3]);
            acc[4] = fmaf(xv, w1.x, acc[4]); acc[5] = fmaf(xv, w1.y, acc[5]);
            acc[6] = fmaf(xv, w1.z, acc[6]); acc[7] = fmaf(xv, w1.w, acc[7]);
        }

        const float4 a0 = *(const float4*)&a[e0];
        const float4 a1 = *(const float4*)&a[e0 + 4];
        if (isL) {
            const float4 b0 = *(const float4*)&lb[e0];
            const float4 b1 = *(const float4*)&lb[e0 + 4];
            acc[0] += b0.x; acc[1] += b0.y; acc[2] += b0.z; acc[3] += b0.w;
            acc[4] += b1.x; acc[5] += b1.y; acc[6] += b1.z; acc[7] += b1.w;
#pragma unroll
            for (int q = 0; q < 8; q++) sLd[(e0 + q) * 8 + k] = bc2(acc[q]);
        } else {
#pragma unroll
            for (int q = 0; q < 8; q++)
                g_R[(b * DD + e0 + q) * KK + i0 + k] = acc[q];
        }
        float p = acc[0] * a0.x + acc[1] * a0.y + acc[2] * a0.z + acc[3] * a0.w +
                  acc[4] * a1.x + acc[5] * a1.y + acc[6] * a1.z + acc[7] * a1.w;
        atomicAdd(isL ? &sSL[k] : &ssR[k], p);
    }
    __syncthreads();

    for (int idx = tid; idx < 1024; idx += 256) {
        int kk = idx >> 7, d = idx & 127;
        g_XT[(b * KK + i0 + kk) * DD + d] = sx[d * 9 + kk];
    }
    if (tid < 8) g_sR[b * KK + i0 + tid] = ssR[tid];
    __syncthreads();

    // ================= grid barrier (all 256 CTAs resident) ================
    if (tid == 0) {
        __threadfence();
        unsigned my_gen = g_gen;
        unsigned arrived = atomicAdd(&g_barc, 1u);
        if (arrived == (unsigned)nblk - 1u) {
            g_barc = 0u;
            __threadfence();
            g_gen = my_gen + 1u;
        } else {
            while (g_gen == my_gen) __nanosleep(40);
        }
        __threadfence();
    }
    __syncthreads();

    // ================= Phase B ============================================
    // ---- e phase: split-d (sp), thread = 4 j (2 packed j-pairs) x 8 i ----
    {
        const int jq = tid & 127;
        const int sp = tid >> 7;
        const float* Rb = g_R + (b * DD + sp * 64) * KK + jq * 4;
        const ull* sLdsp = sLd + sp * 64 * 8;
        const ull* sAdsp = sAd + sp * 64;
        ull acc[8][2];
#pragma unroll
        for (int i = 0; i < 8; i++) { acc[i][0] = 0ull; acc[i][1] = 0ull; }

#pragma unroll 8
        for (int dd = 0; dd < 64; dd++) {
            float4 rq = *(const float4*)(Rb + dd * KK);
            ull r01 = pk2(rq.x, rq.y), r23 = pk2(rq.z, rq.w);
            ull av2 = sAdsp[dd];
#pragma unroll
            for (int i = 0; i < 8; i++) {
                ull l2 = sLdsp[dd * 8 + i];
                ull u0 = uadd2(l2, r01) & ABSM;
                ull u1 = uadd2(l2, r23) & ABSM;
                acc[i][0] = ufma2(u0, av2, acc[i][0]);
                acc[i][1] = ufma2(u1, av2, acc[i][1]);
            }
        }
        float* pp = part + sp * 4096 + jq * 4;
#pragma unroll
        for (int i = 0; i < 8; i++) {
            float2 q0 = up2(acc[i][0]), q1 = up2(acc[i][1]);
            *(float4*)&pp[i * KK] = make_float4(q0.x, q0.y, q1.x, q1.y);
        }
    }
    __syncthreads();

    // ---- combine: e = C1*(sL+sR) + C2*(p0+p1) + bias -> seU[i][j] (dup) ----
    {
        const int jq2 = tid & 127;
        const int ih0 = (tid >> 7) * 4;
        float4 sr = *(const float4*)&g_sR[b * KK + jq2 * 4];
#pragma unroll
        for (int r = 0; r < 4; r++) {
            int i = ih0 + r;
            float4 p0 = *(const float4*)&part[i * KK + jq2 * 4];
            float4 p1 = *(const float4*)&part[4096 + i * KK + jq2 * 4];
            float4 bz = *(const float4*)&bias[(long)(i0 + i) * KK + jq2 * 4];
            float sl = sSL[i];
            ull* dst = seU + i * KK + jq2 * 4;
            dst[0] = bc2(C1 * (sl + sr.x) + C2 * (p0.x + p1.x) + bz.x);
            dst[1] = bc2(C1 * (sl + sr.y) + C2 * (p0.y + p1.y) + bz.y);
            dst[2] = bc2(C1 * (sl + sr.z) + C2 * (p0.z + p1.z) + bz.z);
            dst[3] = bc2(C1 * (sl + sr.w) + C2 * (p0.w + p1.w) + bz.w);
        }
    }
    __syncthreads();

    // ---- softmax: warp w -> row i=w, in-place on dup'd ull entries ----
    {
        const int w = tid >> 5, lane = tid & 31;
        ull* row = seU + w * KK;
        float v[16], m = -3.4e38f;
#pragma unroll
        for (int t = 0; t < 16; t++) { v[t] = up2(row[t * 32 + lane]).x; m = fmaxf(m, v[t]); }
#pragma unroll
        for (int o = 16; o > 0; o >>= 1) m = fmaxf(m, __shfl_xor_sync(0xffffffffu, m, o));
        float s = 0.f;
#pragma unroll
        for (int t = 0; t < 16; t++) { v[t] = __expf(v[t] - m); s += v[t]; }
#pragma unroll
        for (int o = 16; o > 0; o >>= 1) s += __shfl_xor_sync(0xffffffffu, s, o);
        float inv = 1.f / s;
#pragma unroll
        for (int t = 0; t < 16; t++) row[t * 32 + lane] = bc2(v[t] * inv);
    }
    __syncthreads();

    // ---- agg: attn @ XT, thread = (j-slice, d-quad), d packed in pairs ----
    const int d4 = tid & 31;
    const int js = tid >> 5;
    {
        const float* Xb = g_XT + (b * KK + js * 64) * DD + d4 * 4;
        ull ag[8][2];
#pragma unroll
        for (int i = 0; i < 8; i++) { ag[i][0] = 0ull; ag[i][1] = 0ull; }

#pragma unroll 8
        for (int t = 0; t < 64; t++) {
            float4 xq = *(const float4*)(Xb + t * DD);
            ull x01 = pk2(xq.x, xq.y), x23 = pk2(xq.z, xq.w);
            const int j = js * 64 + t;
#pragma unroll
            for (int i = 0; i < 8; i++) {
                ull a2 = seU[i * KK + j];  // broadcast LDS.64, already dup'd
                ag[i][0] = ufma2(a2, x01, ag[i][0]);
                ag[i][1] = ufma2(a2, x23, ag[i][1]);
            }
        }
        float* red = part;  // [js][i][d]
#pragma unroll
        for (int i = 0; i < 8; i++) {
            float2 q0 = up2(ag[i][0]), q1 = up2(ag[i][1]);
            *(float4*)&red[js * 1024 + i * 128 + d4 * 4] =
                make_float4(q0.x, q0.y, q1.x, q1.y);
        }
    }
    __syncthreads();

    // ---- reduce over j-slices + sigmoid + residual ----
    {
        const float* red = part;
        const int i2 = tid >> 5;
        const int dq = (tid & 31) * 4;
        float4 s = make_float4(0.f, 0.f, 0.f, 0.f);
#pragma unroll
        for (int r = 0; r < 8; r++) {
            float4 p = *(const float4*)&red[r * 1024 + i2 * 128 + dq];
            s.x += p.x; s.y += p.y; s.z += p.z; s.w += p.w;
        }
        float4 xt = *(const float4*)&g_XT[(b * KK + i0 + i2) * DD + dq];
        out[(b * DD + dq + 0) * KK + i0 + i2] = 1.f / (1.f + __expf(-s.x)) + xt.x;
        out[(b * DD + dq + 1) * KK + i0 + i2] = 1.f / (1.f + __expf(-s.y)) + xt.y;
        out[(b * DD + dq + 2) * KK + i0 + i2] = 1.f / (1.f + __expf(-s.z)) + xt.z;
        out[(b * DD + dq + 3) * KK + i0 + i2] = 1.f / (1.f + __expf(-s.w)) + xt.w;
    }
}

extern "C" void kernel_launch(void* const* d_in, const int* in_sizes, int n_in,
                              void* d_out, int out_size) {
    const float* x    = (const float*)d_in[0];
    const float* lw   = (const float*)d_in[1];
    const float* lb   = (const float*)d_in[2];
    const float* a    = (const float*)d_in[3];
    const float* bias = (const float*)d_in[4];
    float* out = (float*)d_out;

    static bool attr_set = false;
    if (!attr_set) {
        cudaFuncSetAttribute(kfused, cudaFuncAttributeMaxDynamicSharedMemorySize,
                             SM_FLTS * 4);
        attr_set = true;
    }
    kfused<<<256, 256, SM_FLTS * 4>>>(x, lw, lb, a, bias, out);
}

// round 14
// speedup vs baseline: 1.0966x; 1.0406x over previous
#include <cuda_runtime.h>

#define BB 4
#define DD 128
#define KK 512
// e = C1*(sL+sR) + C2*sum|t|a + bias, with alpha=0.2
#define C1 0.6f
#define C2 0.4f

typedef unsigned long long ull;
#define ABSM 0x7FFFFFFF7FFFFFFFULL

__device__ __forceinline__ ull uadd2(ull a, ull b) {
    ull r; asm("add.rn.f32x2 %0,%1,%2;" : "=l"(r) : "l"(a), "l"(b)); return r;
}
__device__ __forceinline__ ull ufma2(ull a, ull b, ull c) {
    ull r; asm("fma.rn.f32x2 %0,%1,%2,%3;" : "=l"(r) : "l"(a), "l"(b), "l"(c)); return r;
}
__device__ __forceinline__ ull bc2(float x) {
    ull r; asm("mov.b64 %0,{%1,%1};" : "=l"(r) : "f"(x)); return r;
}
__device__ __forceinline__ ull pk2(float x, float y) {
    ull r; asm("mov.b64 %0,{%1,%2};" : "=l"(r) : "f"(x), "f"(y)); return r;
}
__device__ __forceinline__ float2 up2(ull v) {
    float2 f; asm("mov.b64 {%0,%1},%2;" : "=f"(f.x), "=f"(f.y) : "l"(v)); return f;
}

__device__ float g_R[BB * DD * KK];   // [b][e][k]  (d-major)
__device__ float g_XT[BB * KK * DD];  // [b][k][d]
__device__ float g_sR[BB * KK];

// per-b grid barriers (zero-init)
__device__ unsigned int g_barc[BB];
__device__ volatile unsigned int g_gen[BB];

// smem floats: sLd[128][8] dup @0 (2048) | sAd[128] dup @2048 (256)
//              part[2][8][512] @2304 (8192) | se[8][512] @10496 (4096)
#define OF_SAD  2048
#define OF_PART 2304
#define OF_SE   10496
#define SM_FLTS 14592

__global__ __launch_bounds__(256, 2) void kfused(const float* __restrict__ x,
                                                 const float* __restrict__ lw,
                                                 const float* __restrict__ lb,
                                                 const float* __restrict__ a,
                                                 const float* __restrict__ bias,
                                                 float* __restrict__ out) {
    extern __shared__ float sm[];
    ull*   sLd  = (ull*)sm;            // [d][i] dup pairs
    ull*   sAd  = (ull*)(sm + OF_SAD); // [d] dup pairs
    float* part = sm + OF_PART;        // [sp][i][j]  (phase A: sx area)
    float* se   = sm + OF_SE;          // [i][j]
    __shared__ float sSL[8], ssR[8];

    const int tid = threadIdx.x;
    const int b = blockIdx.x >> 6;
    const int i0 = (blockIdx.x & 63) << 3;

    // ================= Phase A: compute L (smem), R/XT/sR (global) =========
    float* sx = part;  // [d][k] pad 9
    for (int idx = tid; idx < 1024; idx += 256) {
        int d = idx >> 3, kk = idx & 7;
        sx[d * 9 + kk] = x[(b * DD + d) * KK + i0 + kk];
    }
    if (tid < 8) { sSL[tid] = 0.f; ssR[tid] = 0.f; }
    if (tid < 128) sAd[tid] = bc2(a[tid]);
    __syncthreads();

    // XT transpose store FIRST — STGs drain while the GEMM below runs
    for (int idx = tid; idx < 1024; idx += 256) {
        int kk = idx >> 7, d = idx & 127;
        g_XT[(b * KK + i0 + kk) * DD + d] = sx[d * 9 + kk];
    }

    {
        const int k = tid & 7;
        const int o8 = tid >> 3;
        const int isL = (o8 < 16);
        const int e0 = (o8 & 15) * 8;
        const float* Wb = lw + (isL ? 0 : 128 * 128) + e0;

        float acc[8] = {0, 0, 0, 0, 0, 0, 0, 0};
#pragma unroll 8
        for (int d = 0; d < 128; d++) {
            float xv = sx[d * 9 + k];
            float4 w0 = *(const float4*)(Wb + d * 128);
            float4 w1 = *(const float4*)(Wb + d * 128 + 4);
            acc[0] = fmaf(xv, w0.x, acc[0]); acc[1] = fmaf(xv, w0.y, acc[1]);
            acc[2] = fmaf(xv, w0.z, acc[2]); acc[3] = fmaf(xv, w0.w, acc[3]);
            acc[4] = fmaf(xv, w1.x, acc[4]); acc[5] = fmaf(xv, w1.y, acc[5]);
            acc[6] = fmaf(xv, w1.z, acc[6]); acc[7] = fmaf(xv, w1.w, acc[7]);
        }

        const float4 a0 = *(const float4*)&a[e0];
        const float4 a1 = *(const float4*)&a[e0 + 4];
        if (isL) {
            const float4 b0 = *(const float4*)&lb[e0];
            const float4 b1 = *(const float4*)&lb[e0 + 4];
            acc[0] += b0.x; acc[1] += b0.y; acc[2] += b0.z; acc[3] += b0.w;
            acc[4] += b1.x; acc[5] += b1.y; acc[6] += b1.z; acc[7] += b1.w;
#pragma unroll
            for (int q = 0; q < 8; q++) sLd[(e0 + q) * 8 + k] = bc2(acc[q]);
        } else {
#pragma unroll
            for (int q = 0; q < 8; q++)
                g_R[(b * DD + e0 + q) * KK + i0 + k] = acc[q];
        }
        float p = acc[0] * a0.x + acc[1] * a0.y + acc[2] * a0.z + acc[3] * a0.w +
                  acc[4] * a1.x + acc[5] * a1.y + acc[6] * a1.z + acc[7] * a1.w;
        atomicAdd(isL ? &sSL[k] : &ssR[k], p);
    }
    __syncthreads();

    if (tid < 8) g_sR[b * KK + i0 + tid] = ssR[tid];
    __syncthreads();

    // ============ per-b grid barrier (64 CTAs each, all resident) ==========
    if (tid == 0) {
        __threadfence();
        unsigned my_gen = g_gen[b];
        unsigned arrived = atomicAdd(&g_barc[b], 1u);
        if (arrived == 63u) {
            g_barc[b] = 0u;
            __threadfence();
            g_gen[b] = my_gen + 1u;
        } else {
            while (g_gen[b] == my_gen) __nanosleep(40);
        }
        __threadfence();
    }
    __syncthreads();

    // ================= Phase B ============================================
    // ---- e phase: split-d (sp), thread = 4 j (2 packed j-pairs) x 8 i ----
    {
        const int jq = tid & 127;
        const int sp = tid >> 7;
        const float* Rb = g_R + (b * DD + sp * 64) * KK + jq * 4;
        const ull* sLdsp = sLd + sp * 64 * 8;
        const ull* sAdsp = sAd + sp * 64;
        ull acc[8][2];
#pragma unroll
        for (int i = 0; i < 8; i++) { acc[i][0] = 0ull; acc[i][1] = 0ull; }

#pragma unroll 8
        for (int dd = 0; dd < 64; dd++) {
            float4 rq = *(const float4*)(Rb + dd * KK);
            ull r01 = pk2(rq.x, rq.y), r23 = pk2(rq.z, rq.w);
            ull av2 = sAdsp[dd];
#pragma unroll
            for (int i = 0; i < 8; i++) {
                ull l2 = sLdsp[dd * 8 + i];
                ull u0 = uadd2(l2, r01) & ABSM;
                ull u1 = uadd2(l2, r23) & ABSM;
                acc[i][0] = ufma2(u0, av2, acc[i][0]);
                acc[i][1] = ufma2(u1, av2, acc[i][1]);
            }
        }
        float* pp = part + sp * 4096 + jq * 4;
#pragma unroll
        for (int i = 0; i < 8; i++) {
            float2 q0 = up2(acc[i][0]), q1 = up2(acc[i][1]);
            *(float4*)&pp[i * KK] = make_float4(q0.x, q0.y, q1.x, q1.y);
        }
    }
    __syncthreads();

    // ---- combine: e = C1*(sL+sR) + C2*(p0+p1) + bias -> se[i][j] ----
    {
        const int jq2 = tid & 127;
        const int ih0 = (tid >> 7) * 4;
        float4 sr = *(const float4*)&g_sR[b * KK + jq2 * 4];
#pragma unroll
        for (int r = 0; r < 4; r++) {
            int i = ih0 + r;
            float4 p0 = *(const float4*)&part[i * KK + jq2 * 4];
            float4 p1 = *(const float4*)&part[4096 + i * KK + jq2 * 4];
            float4 bz = *(const float4*)&bias[(long)(i0 + i) * KK + jq2 * 4];
            float sl = sSL[i];
            float4 ev;
            ev.x = C1 * (sl + sr.x) + C2 * (p0.x + p1.x) + bz.x;
            ev.y = C1 * (sl + sr.y) + C2 * (p0.y + p1.y) + bz.y;
            ev.z = C1 * (sl + sr.z) + C2 * (p0.z + p1.z) + bz.z;
            ev.w = C1 * (sl + sr.w) + C2 * (p0.w + p1.w) + bz.w;
            *(float4*)&se[i * KK + jq2 * 4] = ev;
        }
    }
    __syncthreads();

    // ---- softmax: warp w -> row i=w ----
    {
        const int w = tid >> 5, lane = tid & 31;
        float* row = se + w * KK;
        float v[16], m = -3.4e38f;
#pragma unroll
        for (int t = 0; t < 16; t++) { v[t] = row[t * 32 + lane]; m = fmaxf(m, v[t]); }
#pragma unroll
        for (int o = 16; o > 0; o >>= 1) m = fmaxf(m, __shfl_xor_sync(0xffffffffu, m, o));
        float s = 0.f;
#pragma unroll
        for (int t = 0; t < 16; t++) { v[t] = __expf(v[t] - m); s += v[t]; }
#pragma unroll
        for (int o = 16; o > 0; o >>= 1) s += __shfl_xor_sync(0xffffffffu, s, o);
        float inv = 1.f / s;
#pragma unroll
        for (int t = 0; t < 16; t++) row[t * 32 + lane] = v[t] * inv;
    }
    __syncthreads();

    // ---- agg: attn @ XT, thread = (j-slice, d-quad), d packed in pairs ----
    const int d4 = tid & 31;
    const int js = tid >> 5;
    {
        const float* Xb = g_XT + (b * KK + js * 64) * DD + d4 * 4;
        ull ag[8][2];
#pragma unroll
        for (int i = 0; i < 8; i++) { ag[i][0] = 0ull; ag[i][1] = 0ull; }

#pragma unroll 8
        for (int t = 0; t < 64; t++) {
            float4 xq = *(const float4*)(Xb + t * DD);
            ull x01 = pk2(xq.x, xq.y), x23 = pk2(xq.z, xq.w);
            const int j = js * 64 + t;
#pragma unroll
            for (int i = 0; i < 8; i++) {
                ull a2 = bc2(se[i * KK + j]);
                ag[i][0] = ufma2(a2, x01, ag[i][0]);
                ag[i][1] = ufma2(a2, x23, ag[i][1]);
            }
        }
        float* red = part;  // [js][i][d]
#pragma unroll
        for (int i = 0; i < 8; i++) {
            float2 q0 = up2(ag[i][0]), q1 = up2(ag[i][1]);
            *(float4*)&red[js * 1024 + i * 128 + d4 * 4] =
                make_float4(q0.x, q0.y, q1.x, q1.y);
        }
    }
    __syncthreads();

    // ---- reduce over j-slices + sigmoid + residual ----
    {
        const float* red = part;
        const int i2 = tid >> 5;
        const int dq = (tid & 31) * 4;
        float4 s = make_float4(0.f, 0.f, 0.f, 0.f);
#pragma unroll
        for (int r = 0; r < 8; r++) {
            float4 p = *(const float4*)&red[r * 1024 + i2 * 128 + dq];
            s.x += p.x; s.y += p.y; s.z += p.z; s.w += p.w;
        }
        float4 xt = *(const float4*)&g_XT[(b * KK + i0 + i2) * DD + dq];
        out[(b * DD + dq + 0) * KK + i0 + i2] = 1.f / (1.f + __expf(-s.x)) + xt.x;
        out[(b * DD + dq + 1) * KK + i0 + i2] = 1.f / (1.f + __expf(-s.y)) + xt.y;
        out[(b * DD + dq + 2) * KK + i0 + i2] = 1.f / (1.f + __expf(-s.z)) + xt.z;
        out[(b * DD + dq + 3) * KK + i0 + i2] = 1.f / (1.f + __expf(-s.w)) + xt.w;
    }
}

extern "C" void kernel_launch(void* const* d_in, const int* in_sizes, int n_in,
                              void* d_out, int out_size) {
    const float* x    = (const float*)d_in[0];
    const float* lw   = (const float*)d_in[1];
    const float* lb   = (const float*)d_in[2];
    const float* a    = (const float*)d_in[3];
    const float* bias = (const float*)d_in[4];
    float* out = (float*)d_out;

    static bool attr_set = false;
    if (!attr_set) {
        cudaFuncSetAttribute(kfused, cudaFuncAttributeMaxDynamicSharedMemorySize,
                             SM_FLTS * 4);
        attr_set = true;
    }
    kfused<<<256, 256, SM_FLTS * 4>>>(x, lw, lb, a, bias, out);
}

// round 15
// speedup vs baseline: 1.1007x; 1.0037x over previous
#include <cuda_runtime.h>

#define BB 4
#define DD 128
#define KK 512
// e = C1*(sL+sR) + C2*sum|t|a + bias, with alpha=0.2
#define C1 0.6f
#define C2 0.4f

typedef unsigned long long ull;
#define ABSM 0x7FFFFFFF7FFFFFFFULL

__device__ __forceinline__ ull uadd2(ull a, ull b) {
    ull r; asm("add.rn.f32x2 %0,%1,%2;" : "=l"(r) : "l"(a), "l"(b)); return r;
}
__device__ __forceinline__ ull ufma2(ull a, ull b, ull c) {
    ull r; asm("fma.rn.f32x2 %0,%1,%2,%3;" : "=l"(r) : "l"(a), "l"(b), "l"(c)); return r;
}
__device__ __forceinline__ ull bc2(float x) {
    ull r; asm("mov.b64 %0,{%1,%1};" : "=l"(r) : "f"(x)); return r;
}
__device__ __forceinline__ ull pk2(float x, float y) {
    ull r; asm("mov.b64 %0,{%1,%2};" : "=l"(r) : "f"(x), "f"(y)); return r;
}
__device__ __forceinline__ float2 up2(ull v) {
    float2 f; asm("mov.b64 {%0,%1},%2;" : "=f"(f.x), "=f"(f.y) : "l"(v)); return f;
}

__device__ float g_R[BB * DD * KK];   // [b][e][k]  (d-major)
__device__ float g_XT[BB * KK * DD];  // [b][k][d]
__device__ float g_sR[BB * KK];

// per-b grid barriers (zero-init)
__device__ unsigned int g_barc[BB];
__device__ volatile unsigned int g_gen[BB];

// smem floats: sLd[128][8] dup @0 (2048) | sAd[128] dup @2048 (256)
//              part[2][8][512] @2304 (8192) | se[8][512] @10496 (4096)
#define OF_SAD  2048
#define OF_PART 2304
#define OF_SE   10496
#define SM_FLTS 14592

__global__ __launch_bounds__(256, 2) void kfused(const float* __restrict__ x,
                                                 const float* __restrict__ lw,
                                                 const float* __restrict__ lb,
                                                 const float* __restrict__ a,
                                                 const float* __restrict__ bias,
                                                 float* __restrict__ out) {
    extern __shared__ float sm[];
    ull*   sLd  = (ull*)sm;            // [d][i] dup pairs
    ull*   sAd  = (ull*)(sm + OF_SAD); // [d] dup pairs
    float* part = sm + OF_PART;        // [sp][i][j]  (phase A: sx area)
    float* se   = sm + OF_SE;          // [i][j]
    __shared__ float sSL[8], ssR[8];

    const int tid = threadIdx.x;
    const int b = blockIdx.x >> 6;
    const int i0 = (blockIdx.x & 63) << 3;

    // ================= Phase A: compute L (smem), R/XT/sR (global) =========
    float* sx = part;  // [d][k] pad 9
    for (int idx = tid; idx < 1024; idx += 256) {
        int d = idx >> 3, kk = idx & 7;
        sx[d * 9 + kk] = x[(b * DD + d) * KK + i0 + kk];
    }
    if (tid < 8) { sSL[tid] = 0.f; ssR[tid] = 0.f; }
    if (tid < 128) sAd[tid] = bc2(a[tid]);
    __syncthreads();

    // XT transpose store first — STGs drain while the GEMM below runs
    for (int idx = tid; idx < 1024; idx += 256) {
        int kk = idx >> 7, d = idx & 127;
        g_XT[(b * KK + i0 + kk) * DD + d] = sx[d * 9 + kk];
    }

    {
        const int k = tid & 7;
        const int o8 = tid >> 3;
        const int isL = (o8 < 16);
        const int e0 = (o8 & 15) * 8;
        const float* Wb = lw + (isL ? 0 : 128 * 128) + e0;

        float acc[8] = {0, 0, 0, 0, 0, 0, 0, 0};
#pragma unroll 8
        for (int d = 0; d < 128; d++) {
            float xv = sx[d * 9 + k];
            float4 w0 = *(const float4*)(Wb + d * 128);
            float4 w1 = *(const float4*)(Wb + d * 128 + 4);
            acc[0] = fmaf(xv, w0.x, acc[0]); acc[1] = fmaf(xv, w0.y, acc[1]);
            acc[2] = fmaf(xv, w0.z, acc[2]); acc[3] = fmaf(xv, w0.w, acc[3]);
            acc[4] = fmaf(xv, w1.x, acc[4]); acc[5] = fmaf(xv, w1.y, acc[5]);
            acc[6] = fmaf(xv, w1.z, acc[6]); acc[7] = fmaf(xv, w1.w, acc[7]);
        }

        const float4 a0 = *(const float4*)&a[e0];
        const float4 a1 = *(const float4*)&a[e0 + 4];
        if (isL) {
            const float4 b0 = *(const float4*)&lb[e0];
            const float4 b1 = *(const float4*)&lb[e0 + 4];
            acc[0] += b0.x; acc[1] += b0.y; acc[2] += b0.z; acc[3] += b0.w;
            acc[4] += b1.x; acc[5] += b1.y; acc[6] += b1.z; acc[7] += b1.w;
#pragma unroll
            for (int q = 0; q < 8; q++) sLd[(e0 + q) * 8 + k] = bc2(acc[q]);
        } else {
#pragma unroll
            for (int q = 0; q < 8; q++)
                g_R[(b * DD + e0 + q) * KK + i0 + k] = acc[q];
        }
        float p = acc[0] * a0.x + acc[1] * a0.y + acc[2] * a0.z + acc[3] * a0.w +
                  acc[4] * a1.x + acc[5] * a1.y + acc[6] * a1.z + acc[7] * a1.w;
        atomicAdd(isL ? &sSL[k] : &ssR[k], p);
    }
    __syncthreads();

    if (tid < 8) g_sR[b * KK + i0 + tid] = ssR[tid];
    __syncthreads();

    // ============ per-b grid barrier (64 CTAs each, all resident) ==========
    if (tid == 0) {
        __threadfence();
        unsigned my_gen = g_gen[b];
        unsigned arrived = atomicAdd(&g_barc[b], 1u);
        if (arrived == 63u) {
            g_barc[b] = 0u;
            __threadfence();
            g_gen[b] = my_gen + 1u;
        } else {
            while (g_gen[b] == my_gen) __nanosleep(40);
        }
        __threadfence();
    }
    __syncthreads();

    // ================= Phase B ============================================
    // ---- e phase: split-d (sp), thread = 4 j (2 packed j-pairs) x 8 i ----
    {
        const int jq = tid & 127;
        const int sp = tid >> 7;
        const float* Rb = g_R + (b * DD + sp * 64) * KK + jq * 4;
        const ull* sLdsp = sLd + sp * 64 * 8;
        const ull* sAdsp = sAd + sp * 64;
        ull acc[8][2];
#pragma unroll
        for (int i = 0; i < 8; i++) { acc[i][0] = 0ull; acc[i][1] = 0ull; }

#pragma unroll 8
        for (int dd = 0; dd < 64; dd++) {
            float4 rq = *(const float4*)(Rb + dd * KK);
            ull r01 = pk2(rq.x, rq.y), r23 = pk2(rq.z, rq.w);
            ull av2 = sAdsp[dd];
#pragma unroll
            for (int ip = 0; ip < 4; ip++) {
                ulonglong2 lp = *(const ulonglong2*)&sLdsp[dd * 8 + ip * 2];
                ull u0 = uadd2(lp.x, r01) & ABSM;
                ull u1 = uadd2(lp.x, r23) & ABSM;
                acc[2 * ip][0] = ufma2(u0, av2, acc[2 * ip][0]);
                acc[2 * ip][1] = ufma2(u1, av2, acc[2 * ip][1]);
                ull v0 = uadd2(lp.y, r01) & ABSM;
                ull v1 = uadd2(lp.y, r23) & ABSM;
                acc[2 * ip + 1][0] = ufma2(v0, av2, acc[2 * ip + 1][0]);
                acc[2 * ip + 1][1] = ufma2(v1, av2, acc[2 * ip + 1][1]);
            }
        }
        float* pp = part + sp * 4096 + jq * 4;
#pragma unroll
        for (int i = 0; i < 8; i++) {
            float2 q0 = up2(acc[i][0]), q1 = up2(acc[i][1]);
            *(float4*)&pp[i * KK] = make_float4(q0.x, q0.y, q1.x, q1.y);
        }
    }
    __syncthreads();

    // ---- combine: e = C1*(sL+sR) + C2*(p0+p1) + bias -> se[i][j] ----
    {
        const int jq2 = tid & 127;
        const int ih0 = (tid >> 7) * 4;
        float4 sr = *(const float4*)&g_sR[b * KK + jq2 * 4];
#pragma unroll
        for (int r = 0; r < 4; r++) {
            int i = ih0 + r;
            float4 p0 = *(const float4*)&part[i * KK + jq2 * 4];
            float4 p1 = *(const float4*)&part[4096 + i * KK + jq2 * 4];
            float4 bz = *(const float4*)&bias[(long)(i0 + i) * KK + jq2 * 4];
            float sl = sSL[i];
            float4 ev;
            ev.x = C1 * (sl + sr.x) + C2 * (p0.x + p1.x) + bz.x;
            ev.y = C1 * (sl + sr.y) + C2 * (p0.y + p1.y) + bz.y;
            ev.z = C1 * (sl + sr.z) + C2 * (p0.z + p1.z) + bz.z;
            ev.w = C1 * (sl + sr.w) + C2 * (p0.w + p1.w) + bz.w;
            *(float4*)&se[i * KK + jq2 * 4] = ev;
        }
    }
    __syncthreads();

    // ---- softmax: warp w -> row i=w ----
    {
        const int w = tid >> 5, lane = tid & 31;
        float* row = se + w * KK;
        float v[16], m = -3.4e38f;
#pragma unroll
        for (int t = 0; t < 16; t++) { v[t] = row[t * 32 + lane]; m = fmaxf(m, v[t]); }
#pragma unroll
        for (int o = 16; o > 0; o >>= 1) m = fmaxf(m, __shfl_xor_sync(0xffffffffu, m, o));
        float s = 0.f;
#pragma unroll
        for (int t = 0; t < 16; t++) { v[t] = __expf(v[t] - m); s += v[t]; }
#pragma unroll
        for (int o = 16; o > 0; o >>= 1) s += __shfl_xor_sync(0xffffffffu, s, o);
        float inv = 1.f / s;
#pragma unroll
        for (int t = 0; t < 16; t++) row[t * 32 + lane] = v[t] * inv;
    }
    __syncthreads();

    // ---- agg: attn @ XT, thread = (j-slice, d-quad), d packed in pairs ----
    const int d4 = tid & 31;
    const int js = tid >> 5;
    {
        const float* Xb = g_XT + (b * KK + js * 64) * DD + d4 * 4;
        ull ag[8][2];
#pragma unroll
        for (int i = 0; i < 8; i++) { ag[i][0] = 0ull; ag[i][1] = 0ull; }

#pragma unroll 8
        for (int t = 0; t < 64; t++) {
            float4 xq = *(const float4*)(Xb + t * DD);
            ull x01 = pk2(xq.x, xq.y), x23 = pk2(xq.z, xq.w);
            const int j = js * 64 + t;
#pragma unroll
            for (int i = 0; i < 8; i++) {
                ull a2 = bc2(se[i * KK + j]);
                ag[i][0] = ufma2(a2, x01, ag[i][0]);
                ag[i][1] = ufma2(a2, x23, ag[i][1]);
            }
        }
        float* red = part;  // [js][i][d]
#pragma unroll
        for (int i = 0; i < 8; i++) {
            float2 q0 = up2(ag[i][0]), q1 = up2(ag[i][1]);
            *(float4*)&red[js * 1024 + i * 128 + d4 * 4] =
                make_float4(q0.x, q0.y, q1.x, q1.y);
        }
    }
    __syncthreads();

    // ---- reduce over j-slices + sigmoid + residual ----
    {
        const float* red = part;
        const int i2 = tid >> 5;
        const int dq = (tid & 31) * 4;
        float4 s = make_float4(0.f, 0.f, 0.f, 0.f);
#pragma unroll
        for (int r = 0; r < 8; r++) {
            float4 p = *(const float4*)&red[r * 1024 + i2 * 128 + dq];
            s.x += p.x; s.y += p.y; s.z += p.z; s.w += p.w;
        }
        float4 xt = *(const float4*)&g_XT[(b * KK + i0 + i2) * DD + dq];
        out[(b * DD + dq + 0) * KK + i0 + i2] = 1.f / (1.f + __expf(-s.x)) + xt.x;
        out[(b * DD + dq + 1) * KK + i0 + i2] = 1.f / (1.f + __expf(-s.y)) + xt.y;
        out[(b * DD + dq + 2) * KK + i0 + i2] = 1.f / (1.f + __expf(-s.z)) + xt.z;
        out[(b * DD + dq + 3) * KK + i0 + i2] = 1.f / (1.f + __expf(-s.w)) + xt.w;
    }
}

extern "C" void kernel_launch(void* const* d_in, const int* in_sizes, int n_in,
                              void* d_out, int out_size) {
    const float* x    = (const float*)d_in[0];
    const float* lw   = (const float*)d_in[1];
    const float* lb   = (const float*)d_in[2];
    const float* a    = (const float*)d_in[3];
    const float* bias = (const float*)d_in[4];
    float* out = (float*)d_out;

    static bool attr_set = false;
    if (!attr_set) {
        cudaFuncSetAttribute(kfused, cudaFuncAttributeMaxDynamicSharedMemorySize,
                             SM_FLTS * 4);
        attr_set = true;
    }
    kfused<<<256, 256, SM_FLTS * 4>>>(x, lw, lb, a, bias, out);
}

// round 16
// speedup vs baseline: 1.2002x; 1.0904x over previous
#include <cuda_runtime.h>

#define BB 4
#define DD 128
#define KK 512
// e = C1*(sL+sR) + C2*sum|t|a + bias, with alpha=0.2
#define C1 0.6f
#define C2 0.4f

typedef unsigned long long ull;

__device__ __forceinline__ ull uadd2(ull a, ull b) {
    ull r; asm("add.rn.f32x2 %0,%1,%2;" : "=l"(r) : "l"(a), "l"(b)); return r;
}
__device__ __forceinline__ ull ufma2(ull a, ull b, ull c) {
    ull r; asm("fma.rn.f32x2 %0,%1,%2,%3;" : "=l"(r) : "l"(a), "l"(b), "l"(c)); return r;
}
__device__ __forceinline__ ull bc2(float x) {
    ull r; asm("mov.b64 %0,{%1,%1};" : "=l"(r) : "f"(x)); return r;
}
__device__ __forceinline__ ull pk2(float x, float y) {
    ull r; asm("mov.b64 %0,{%1,%2};" : "=l"(r) : "f"(x), "f"(y)); return r;
}
__device__ __forceinline__ float2 up2(ull v) {
    float2 f; asm("mov.b64 {%0,%1},%2;" : "=f"(f.x), "=f"(f.y) : "l"(v)); return f;
}

__device__ float g_R[BB * DD * KK];   // [b][e][k]  (d-major)
__device__ float g_XT[BB * KK * DD];  // [b][k][d]
__device__ float g_sR[BB * KK];

// per-b grid barriers (zero-init)
__device__ unsigned int g_barc[BB];
__device__ volatile unsigned int g_gen[BB];

// smem floats: sLd[128][8] dup @0 (2048) | sAd[128] dup @2048 (256)
//              part[2][8][512] @2304 (8192) | se[8][512] @10496 (4096)
#define OF_SAD  2048
#define OF_PART 2304
#define OF_SE   10496
#define SM_FLTS 14592

__global__ __launch_bounds__(256, 2) void kfused(const float* __restrict__ x,
                                                 const float* __restrict__ lw,
                                                 const float* __restrict__ lb,
                                                 const float* __restrict__ a,
                                                 const float* __restrict__ bias,
                                                 float* __restrict__ out) {
    extern __shared__ float sm[];
    ull*   sLd  = (ull*)sm;            // [d][i] dup pairs
    ull*   sAd  = (ull*)(sm + OF_SAD); // [d] dup pairs
    float* part = sm + OF_PART;        // [sp][i][j]  (phase A: sx area)
    float* se   = sm + OF_SE;          // [i][j]
    __shared__ float sSL[8], ssR[8];

    const int tid = threadIdx.x;
    const int b = blockIdx.x >> 6;
    const int i0 = (blockIdx.x & 63) << 3;

    // ================= Phase A: compute L (smem), R/XT/sR (global) =========
    float* sx = part;  // [d][k] pad 9
    for (int idx = tid; idx < 1024; idx += 256) {
        int d = idx >> 3, kk = idx & 7;
        sx[d * 9 + kk] = x[(b * DD + d) * KK + i0 + kk];
    }
    if (tid < 8) { sSL[tid] = 0.f; ssR[tid] = 0.f; }
    if (tid < 128) sAd[tid] = bc2(a[tid]);
    __syncthreads();

    // XT transpose store first — STGs drain while the GEMM below runs
    for (int idx = tid; idx < 1024; idx += 256) {
        int kk = idx >> 7, d = idx & 127;
        g_XT[(b * KK + i0 + kk) * DD + d] = sx[d * 9 + kk];
    }

    {
        const int k = tid & 7;
        const int o8 = tid >> 3;
        const int isL = (o8 < 16);
        const int e0 = (o8 & 15) * 8;
        const float* Wb = lw + (isL ? 0 : 128 * 128) + e0;

        float acc[8] = {0, 0, 0, 0, 0, 0, 0, 0};
#pragma unroll 8
        for (int d = 0; d < 128; d++) {
            float xv = sx[d * 9 + k];
            float4 w0 = *(const float4*)(Wb + d * 128);
            float4 w1 = *(const float4*)(Wb + d * 128 + 4);
            acc[0] = fmaf(xv, w0.x, acc[0]); acc[1] = fmaf(xv, w0.y, acc[1]);
            acc[2] = fmaf(xv, w0.z, acc[2]); acc[3] = fmaf(xv, w0.w, acc[3]);
            acc[4] = fmaf(xv, w1.x, acc[4]); acc[5] = fmaf(xv, w1.y, acc[5]);
            acc[6] = fmaf(xv, w1.z, acc[6]); acc[7] = fmaf(xv, w1.w, acc[7]);
        }

        const float4 a0 = *(const float4*)&a[e0];
        const float4 a1 = *(const float4*)&a[e0 + 4];
        if (isL) {
            const float4 b0 = *(const float4*)&lb[e0];
            const float4 b1 = *(const float4*)&lb[e0 + 4];
            acc[0] += b0.x; acc[1] += b0.y; acc[2] += b0.z; acc[3] += b0.w;
            acc[4] += b1.x; acc[5] += b1.y; acc[6] += b1.z; acc[7] += b1.w;
#pragma unroll
            for (int q = 0; q < 8; q++) sLd[(e0 + q) * 8 + k] = bc2(acc[q]);
        } else {
#pragma unroll
            for (int q = 0; q < 8; q++)
                g_R[(b * DD + e0 + q) * KK + i0 + k] = acc[q];
        }
        float p = acc[0] * a0.x + acc[1] * a0.y + acc[2] * a0.z + acc[3] * a0.w +
                  acc[4] * a1.x + acc[5] * a1.y + acc[6] * a1.z + acc[7] * a1.w;
        atomicAdd(isL ? &sSL[k] : &ssR[k], p);
    }
    __syncthreads();

    if (tid < 8) g_sR[b * KK + i0 + tid] = ssR[tid];
    __syncthreads();

    // ============ per-b grid barrier (64 CTAs each, all resident) ==========
    if (tid == 0) {
        __threadfence();
        unsigned my_gen = g_gen[b];
        unsigned arrived = atomicAdd(&g_barc[b], 1u);
        if (arrived == 63u) {
            g_barc[b] = 0u;
            __threadfence();
            g_gen[b] = my_gen + 1u;
        } else {
            while (g_gen[b] == my_gen) __nanosleep(40);
        }
        __threadfence();
    }
    __syncthreads();

    // ================= Phase B ============================================
    // ---- e phase: split-d (sp), thread = 4 j x 8 i; packed add, |.| in FFMA
    {
        const int jq = tid & 127;
        const int sp = tid >> 7;
        const float* Rb = g_R + (b * DD + sp * 64) * KK + jq * 4;
        const ull* sLdsp = sLd + sp * 64 * 8;
        const ull* sAdsp = sAd + sp * 64;
        float acc[8][4];
#pragma unroll
        for (int i = 0; i < 8; i++) {
            acc[i][0] = 0.f; acc[i][1] = 0.f; acc[i][2] = 0.f; acc[i][3] = 0.f;
        }

#pragma unroll 8
        for (int dd = 0; dd < 64; dd++) {
            float4 rq = *(const float4*)(Rb + dd * KK);
            ull r01 = pk2(rq.x, rq.y), r23 = pk2(rq.z, rq.w);
            float av = up2(sAdsp[dd]).x;
#pragma unroll
            for (int ip = 0; ip < 4; ip++) {
                ulonglong2 lp = *(const ulonglong2*)&sLdsp[dd * 8 + ip * 2];
                const int i = 2 * ip;
                float2 ta = up2(uadd2(lp.x, r01));
                float2 tb = up2(uadd2(lp.x, r23));
                acc[i][0] = fmaf(fabsf(ta.x), av, acc[i][0]);
                acc[i][1] = fmaf(fabsf(ta.y), av, acc[i][1]);
                acc[i][2] = fmaf(fabsf(tb.x), av, acc[i][2]);
                acc[i][3] = fmaf(fabsf(tb.y), av, acc[i][3]);
                float2 tc = up2(uadd2(lp.y, r01));
                float2 td = up2(uadd2(lp.y, r23));
                acc[i + 1][0] = fmaf(fabsf(tc.x), av, acc[i + 1][0]);
                acc[i + 1][1] = fmaf(fabsf(tc.y), av, acc[i + 1][1]);
                acc[i + 1][2] = fmaf(fabsf(td.x), av, acc[i + 1][2]);
                acc[i + 1][3] = fmaf(fabsf(td.y), av, acc[i + 1][3]);
            }
        }
        float* pp = part + sp * 4096 + jq * 4;
#pragma unroll
        for (int i = 0; i < 8; i++)
            *(float4*)&pp[i * KK] =
                make_float4(acc[i][0], acc[i][1], acc[i][2], acc[i][3]);
    }
    __syncthreads();

    // ---- combine: e = C1*(sL+sR) + C2*(p0+p1) + bias -> se[i][j] ----
    {
        const int jq2 = tid & 127;
        const int ih0 = (tid >> 7) * 4;
        float4 sr = *(const float4*)&g_sR[b * KK + jq2 * 4];
#pragma unroll
        for (int r = 0; r < 4; r++) {
            int i = ih0 + r;
            float4 p0 = *(const float4*)&part[i * KK + jq2 * 4];
            float4 p1 = *(const float4*)&part[4096 + i * KK + jq2 * 4];
            float4 bz = *(const float4*)&bias[(long)(i0 + i) * KK + jq2 * 4];
            float sl = sSL[i];
            float4 ev;
            ev.x = C1 * (sl + sr.x) + C2 * (p0.x + p1.x) + bz.x;
            ev.y = C1 * (sl + sr.y) + C2 * (p0.y + p1.y) + bz.y;
            ev.z = C1 * (sl + sr.z) + C2 * (p0.z + p1.z) + bz.z;
            ev.w = C1 * (sl + sr.w) + C2 * (p0.w + p1.w) + bz.w;
            *(float4*)&se[i * KK + jq2 * 4] = ev;
        }
    }
    __syncthreads();

    // ---- softmax: warp w -> row i=w ----
    {
        const int w = tid >> 5, lane = tid & 31;
        float* row = se + w * KK;
        float v[16], m = -3.4e38f;
#pragma unroll
        for (int t = 0; t < 16; t++) { v[t] = row[t * 32 + lane]; m = fmaxf(m, v[t]); }
#pragma unroll
        for (int o = 16; o > 0; o >>= 1) m = fmaxf(m, __shfl_xor_sync(0xffffffffu, m, o));
        float s = 0.f;
#pragma unroll
        for (int t = 0; t < 16; t++) { v[t] = __expf(v[t] - m); s += v[t]; }
#pragma unroll
        for (int o = 16; o > 0; o >>= 1) s += __shfl_xor_sync(0xffffffffu, s, o);
        float inv = 1.f / s;
#pragma unroll
        for (int t = 0; t < 16; t++) row[t * 32 + lane] = v[t] * inv;
    }
    __syncthreads();

    // ---- agg: attn @ XT, thread = (j-slice, d-quad), d packed in pairs ----
    const int d4 = tid & 31;
    const int js = tid >> 5;
    {
        const float* Xb = g_XT + (b * KK + js * 64) * DD + d4 * 4;
        ull ag[8][2];
#pragma unroll
        for (int i = 0; i < 8; i++) { ag[i][0] = 0ull; ag[i][1] = 0ull; }

#pragma unroll 8
        for (int t = 0; t < 64; t++) {
            float4 xq = *(const float4*)(Xb + t * DD);
            ull x01 = pk2(xq.x, xq.y), x23 = pk2(xq.z, xq.w);
            const int j = js * 64 + t;
#pragma unroll
            for (int i = 0; i < 8; i++) {
                ull a2 = bc2(se[i * KK + j]);
                ag[i][0] = ufma2(a2, x01, ag[i][0]);
                ag[i][1] = ufma2(a2, x23, ag[i][1]);
            }
        }
        float* red = part;  // [js][i][d]
#pragma unroll
        for (int i = 0; i < 8; i++) {
            float2 q0 = up2(ag[i][0]), q1 = up2(ag[i][1]);
            *(float4*)&red[js * 1024 + i * 128 + d4 * 4] =
                make_float4(q0.x, q0.y, q1.x, q1.y);
        }
    }
    __syncthreads();

    // ---- reduce over j-slices + sigmoid + residual ----
    {
        const float* red = part;
        const int i2 = tid >> 5;
        const int dq = (tid & 31) * 4;
        float4 s = make_float4(0.f, 0.f, 0.f, 0.f);
#pragma unroll
        for (int r = 0; r < 8; r++) {
            float4 p = *(const float4*)&red[r * 1024 + i2 * 128 + dq];
            s.x += p.x; s.y += p.y; s.z += p.z; s.w += p.w;
        }
        float4 xt = *(const float4*)&g_XT[(b * KK + i0 + i2) * DD + dq];
        out[(b * DD + dq + 0) * KK + i0 + i2] = 1.f / (1.f + __expf(-s.x)) + xt.x;
        out[(b * DD + dq + 1) * KK + i0 + i2] = 1.f / (1.f + __expf(-s.y)) + xt.y;
        out[(b * DD + dq + 2) * KK + i0 + i2] = 1.f / (1.f + __expf(-s.z)) + xt.z;
        out[(b * DD + dq + 3) * KK + i0 + i2] = 1.f / (1.f + __expf(-s.w)) + xt.w;
    }
}

extern "C" void kernel_launch(void* const* d_in, const int* in_sizes, int n_in,
                              void* d_out, int out_size) {
    const float* x    = (const float*)d_in[0];
    const float* lw   = (const float*)d_in[1];
    const float* lb   = (const float*)d_in[2];
    const float* a    = (const float*)d_in[3];
    const float* bias = (const float*)d_in[4];
    float* out = (float*)d_out;

    static bool attr_set = false;
    if (!attr_set) {
        cudaFuncSetAttribute(kfused, cudaFuncAttributeMaxDynamicSharedMemorySize,
                             SM_FLTS * 4);
        attr_set = true;
    }
    kfused<<<256, 256, SM_FLTS * 4>>>(x, lw, lb, a, bias, out);
}

// round 17
// speedup vs baseline: 1.2080x; 1.0065x over previous
#include <cuda_runtime.h>

#define BB 4
#define DD 128
#define KK 512
// e = C1*(sL+sR) + C2*sum|t|a + bias, with alpha=0.2
#define C1 0.6f
#define C2 0.4f

typedef unsigned long long ull;

__device__ __forceinline__ ull uadd2(ull a, ull b) {
    ull r; asm("add.rn.f32x2 %0,%1,%2;" : "=l"(r) : "l"(a), "l"(b)); return r;
}
__device__ __forceinline__ ull ufma2(ull a, ull b, ull c) {
    ull r; asm("fma.rn.f32x2 %0,%1,%2,%3;" : "=l"(r) : "l"(a), "l"(b), "l"(c)); return r;
}
__device__ __forceinline__ ull bc2(float x) {
    ull r; asm("mov.b64 %0,{%1,%1};" : "=l"(r) : "f"(x)); return r;
}
__device__ __forceinline__ ull pk2(float x, float y) {
    ull r; asm("mov.b64 %0,{%1,%2};" : "=l"(r) : "f"(x), "f"(y)); return r;
}
__device__ __forceinline__ float2 up2(ull v) {
    float2 f; asm("mov.b64 {%0,%1},%2;" : "=f"(f.x), "=f"(f.y) : "l"(v)); return f;
}
// pack two f32 into bf16x2 (lo, hi)
__device__ __forceinline__ unsigned bfpack(float lo, float hi) {
    unsigned r; asm("cvt.rn.bf16x2.f32 %0,%1,%2;" : "=r"(r) : "f"(hi), "f"(lo)); return r;
}
// unpack bf16x2 -> two f32 via shift/mask (alu pipe)
__device__ __forceinline__ float bflo(unsigned v) { return __uint_as_float(v << 16); }
__device__ __forceinline__ float bfhi(unsigned v) { return __uint_as_float(v & 0xFFFF0000u); }

__device__ float g_R[BB * DD * KK];    // [b][e][k]  (d-major)
__device__ float g_XT[BB * KK * DD];   // [b][k][d]  f32 (epilogue residual)
__device__ unsigned g_XTh[BB * KK * 64];  // [b][k][d/2] bf16x2 (agg operand)
__device__ float g_sR[BB * KK];

// per-b grid barriers (zero-init)
__device__ unsigned int g_barc[BB];
__device__ volatile unsigned int g_gen[BB];

// smem floats: sLd[128][8] dup @0 (2048) | sAd[128] dup @2048 (256)
//              part[2][8][512] @2304 (8192) | se[8][512] @10496 (4096)
#define OF_SAD  2048
#define OF_PART 2304
#define OF_SE   10496
#define SM_FLTS 14592

__global__ __launch_bounds__(256, 2) void kfused(const float* __restrict__ x,
                                                 const float* __restrict__ lw,
                                                 const float* __restrict__ lb,
                                                 const float* __restrict__ a,
                                                 const float* __restrict__ bias,
                                                 float* __restrict__ out) {
    extern __shared__ float sm[];
    ull*   sLd  = (ull*)sm;            // [d][i] dup pairs
    ull*   sAd  = (ull*)(sm + OF_SAD); // [d] dup pairs
    float* part = sm + OF_PART;        // [sp][i][j]  (phase A: sx area)
    float* se   = sm + OF_SE;          // [i][j]
    __shared__ float sSL[8], ssR[8];

    const int tid = threadIdx.x;
    const int b = blockIdx.x >> 6;
    const int i0 = (blockIdx.x & 63) << 3;

    // ================= Phase A: compute L (smem), R/XT/sR (global) =========
    float* sx = part;  // [d][k] pad 9
    for (int idx = tid; idx < 1024; idx += 256) {
        int d = idx >> 3, kk = idx & 7;
        sx[d * 9 + kk] = x[(b * DD + d) * KK + i0 + kk];
    }
    if (tid < 8) { sSL[tid] = 0.f; ssR[tid] = 0.f; }
    if (tid < 128) sAd[tid] = bc2(a[tid]);
    __syncthreads();

    // XT stores first — STGs drain while the GEMM below runs
    for (int idx = tid; idx < 1024; idx += 256) {
        int kk = idx >> 7, d = idx & 127;
        g_XT[(b * KK + i0 + kk) * DD + d] = sx[d * 9 + kk];
    }
    for (int idx = tid; idx < 512; idx += 256) {
        int kk = idx >> 6, dp = idx & 63;
        float lo = sx[(2 * dp) * 9 + kk];
        float hi = sx[(2 * dp + 1) * 9 + kk];
        g_XTh[(b * KK + i0 + kk) * 64 + dp] = bfpack(lo, hi);
    }

    {
        const int k = tid & 7;
        const int o8 = tid >> 3;
        const int isL = (o8 < 16);
        const int e0 = (o8 & 15) * 8;
        const float* Wb = lw + (isL ? 0 : 128 * 128) + e0;

        ull ac01 = 0ull, ac23 = 0ull, ac45 = 0ull, ac67 = 0ull;
#pragma unroll 8
        for (int d = 0; d < 128; d++) {
            ull xv2 = bc2(sx[d * 9 + k]);
            ulonglong2 w0 = *(const ulonglong2*)(Wb + d * 128);
            ulonglong2 w1 = *(const ulonglong2*)(Wb + d * 128 + 4);
            ac01 = ufma2(xv2, w0.x, ac01);
            ac23 = ufma2(xv2, w0.y, ac23);
            ac45 = ufma2(xv2, w1.x, ac45);
            ac67 = ufma2(xv2, w1.y, ac67);
        }
        float acc[8];
        { float2 q = up2(ac01); acc[0] = q.x; acc[1] = q.y; }
        { float2 q = up2(ac23); acc[2] = q.x; acc[3] = q.y; }
        { float2 q = up2(ac45); acc[4] = q.x; acc[5] = q.y; }
        { float2 q = up2(ac67); acc[6] = q.x; acc[7] = q.y; }

        const float4 a0 = *(const float4*)&a[e0];
        const float4 a1 = *(const float4*)&a[e0 + 4];
        if (isL) {
            const float4 b0 = *(const float4*)&lb[e0];
            const float4 b1 = *(const float4*)&lb[e0 + 4];
            acc[0] += b0.x; acc[1] += b0.y; acc[2] += b0.z; acc[3] += b0.w;
            acc[4] += b1.x; acc[5] += b1.y; acc[6] += b1.z; acc[7] += b1.w;
#pragma unroll
            for (int q = 0; q < 8; q++) sLd[(e0 + q) * 8 + k] = bc2(acc[q]);
        } else {
#pragma unroll
            for (int q = 0; q < 8; q++)
                g_R[(b * DD + e0 + q) * KK + i0 + k] = acc[q];
        }
        float p = acc[0] * a0.x + acc[1] * a0.y + acc[2] * a0.z + acc[3] * a0.w +
                  acc[4] * a1.x + acc[5] * a1.y + acc[6] * a1.z + acc[7] * a1.w;
        atomicAdd(isL ? &sSL[k] : &ssR[k], p);
    }
    __syncthreads();

    if (tid < 8) g_sR[b * KK + i0 + tid] = ssR[tid];
    __syncthreads();

    // ============ per-b grid barrier (64 CTAs each, all resident) ==========
    if (tid == 0) {
        __threadfence();
        unsigned my_gen = g_gen[b];
        unsigned arrived = atomicAdd(&g_barc[b], 1u);
        if (arrived == 63u) {
            g_barc[b] = 0u;
            __threadfence();
            g_gen[b] = my_gen + 1u;
        } else {
            while (g_gen[b] == my_gen) __nanosleep(40);
        }
        __threadfence();
    }
    __syncthreads();

    // ================= Phase B ============================================
    // ---- e phase: split-d (sp), thread = 4 j x 8 i; packed add, |.| in FFMA
    {
        const int jq = tid & 127;
        const int sp = tid >> 7;
        const float* Rb = g_R + (b * DD + sp * 64) * KK + jq * 4;
        const ull* sLdsp = sLd + sp * 64 * 8;
        const ull* sAdsp = sAd + sp * 64;
        float acc[8][4];
#pragma unroll
        for (int i = 0; i < 8; i++) {
            acc[i][0] = 0.f; acc[i][1] = 0.f; acc[i][2] = 0.f; acc[i][3] = 0.f;
        }

#pragma unroll 8
        for (int dd = 0; dd < 64; dd++) {
            float4 rq = *(const float4*)(Rb + dd * KK);
            ull r01 = pk2(rq.x, rq.y), r23 = pk2(rq.z, rq.w);
            float av = up2(sAdsp[dd]).x;
#pragma unroll
            for (int ip = 0; ip < 4; ip++) {
                ulonglong2 lp = *(const ulonglong2*)&sLdsp[dd * 8 + ip * 2];
                const int i = 2 * ip;
                float2 ta = up2(uadd2(lp.x, r01));
                float2 tb = up2(uadd2(lp.x, r23));
                acc[i][0] = fmaf(fabsf(ta.x), av, acc[i][0]);
                acc[i][1] = fmaf(fabsf(ta.y), av, acc[i][1]);
                acc[i][2] = fmaf(fabsf(tb.x), av, acc[i][2]);
                acc[i][3] = fmaf(fabsf(tb.y), av, acc[i][3]);
                float2 tc = up2(uadd2(lp.y, r01));
                float2 td = up2(uadd2(lp.y, r23));
                acc[i + 1][0] = fmaf(fabsf(tc.x), av, acc[i + 1][0]);
                acc[i + 1][1] = fmaf(fabsf(tc.y), av, acc[i + 1][1]);
                acc[i + 1][2] = fmaf(fabsf(td.x), av, acc[i + 1][2]);
                acc[i + 1][3] = fmaf(fabsf(td.y), av, acc[i + 1][3]);
            }
        }
        float* pp = part + sp * 4096 + jq * 4;
#pragma unroll
        for (int i = 0; i < 8; i++)
            *(float4*)&pp[i * KK] =
                make_float4(acc[i][0], acc[i][1], acc[i][2], acc[i][3]);
    }
    __syncthreads();

    // ---- combine: e = C1*(sL+sR) + C2*(p0+p1) + bias -> se[i][j] ----
    {
        const int jq2 = tid & 127;
        const int ih0 = (tid >> 7) * 4;
        float4 sr = *(const float4*)&g_sR[b * KK + jq2 * 4];
#pragma unroll
        for (int r = 0; r < 4; r++) {
            int i = ih0 + r;
            float4 p0 = *(const float4*)&part[i * KK + jq2 * 4];
            float4 p1 = *(const float4*)&part[4096 + i * KK + jq2 * 4];
            float4 bz = *(const float4*)&bias[(long)(i0 + i) * KK + jq2 * 4];
            float sl = sSL[i];
            float4 ev;
            ev.x = C1 * (sl + sr.x) + C2 * (p0.x + p1.x) + bz.x;
            ev.y = C1 * (sl + sr.y) + C2 * (p0.y + p1.y) + bz.y;
            ev.z = C1 * (sl + sr.z) + C2 * (p0.z + p1.z) + bz.z;
            ev.w = C1 * (sl + sr.w) + C2 * (p0.w + p1.w) + bz.w;
            *(float4*)&se[i * KK + jq2 * 4] = ev;
        }
    }
    __syncthreads();

    // ---- softmax: warp w -> row i=w ----
    {
        const int w = tid >> 5, lane = tid & 31;
        float* row = se + w * KK;
        float v[16], m = -3.4e38f;
#pragma unroll
        for (int t = 0; t < 16; t++) { v[t] = row[t * 32 + lane]; m = fmaxf(m, v[t]); }
#pragma unroll
        for (int o = 16; o > 0; o >>= 1) m = fmaxf(m, __shfl_xor_sync(0xffffffffu, m, o));
        float s = 0.f;
#pragma unroll
        for (int t = 0; t < 16; t++) { v[t] = __expf(v[t] - m); s += v[t]; }
#pragma unroll
        for (int o = 16; o > 0; o >>= 1) s += __shfl_xor_sync(0xffffffffu, s, o);
        float inv = 1.f / s;
#pragma unroll
        for (int t = 0; t < 16; t++) row[t * 32 + lane] = v[t] * inv;
    }
    __syncthreads();

    // ---- agg: attn @ XT(bf16), thread = (j-slice, d-quad) ----
    const int d4 = tid & 31;
    const int js = tid >> 5;
    {
        const unsigned* Xh = g_XTh + (b * KK + js * 64) * 64 + d4 * 2;
        ull ag[8][2];
#pragma unroll
        for (int i = 0; i < 8; i++) { ag[i][0] = 0ull; ag[i][1] = 0ull; }

#pragma unroll 8
        for (int t = 0; t < 64; t++) {
            uint2 xv = *(const uint2*)(Xh + t * 64);
            ull x01 = pk2(bflo(xv.x), bfhi(xv.x));
            ull x23 = pk2(bflo(xv.y), bfhi(xv.y));
            const int j = js * 64 + t;
#pragma unroll
            for (int i = 0; i < 8; i++) {
                ull a2 = bc2(se[i * KK + j]);
                ag[i][0] = ufma2(a2, x01, ag[i][0]);
                ag[i][1] = ufma2(a2, x23, ag[i][1]);
            }
        }
        float* red = part;  // [js][i][d]
#pragma unroll
        for (int i = 0; i < 8; i++) {
            float2 q0 = up2(ag[i][0]), q1 = up2(ag[i][1]);
            *(float4*)&red[js * 1024 + i * 128 + d4 * 4] =
                make_float4(q0.x, q0.y, q1.x, q1.y);
        }
    }
    __syncthreads();

    // ---- reduce over j-slices + sigmoid + residual ----
    {
        const float* red = part;
        const int i2 = tid >> 5;
        const int dq = (tid & 31) * 4;
        float4 s = make_float4(0.f, 0.f, 0.f, 0.f);
#pragma unroll
        for (int r = 0; r < 8; r++) {
            float4 p = *(const float4*)&red[r * 1024 + i2 * 128 + dq];
            s.x += p.x; s.y += p.y; s.z += p.z; s.w += p.w;
        }
        float4 xt = *(const float4*)&g_XT[(b * KK + i0 + i2) * DD + dq];
        out[(b * DD + dq + 0) * KK + i0 + i2] = 1.f / (1.f + __expf(-s.x)) + xt.x;
        out[(b * DD + dq + 1) * KK + i0 + i2] = 1.f / (1.f + __expf(-s.y)) + xt.y;
        out[(b * DD + dq + 2) * KK + i0 + i2] = 1.f / (1.f + __expf(-s.z)) + xt.z;
        out[(b * DD + dq + 3) * KK + i0 + i2] = 1.f / (1.f + __expf(-s.w)) + xt.w;
    }
}

extern "C" void kernel_launch(void* const* d_in, const int* in_sizes, int n_in,
                              void* d_out, int out_size) {
    const float* x    = (const float*)d_in[0];
    const float* lw   = (const float*)d_in[1];
    const float* lb   = (const float*)d_in[2];
    const float* a    = (const float*)d_in[3];
    const float* bias = (const float*)d_in[4];
    float* out = (float*)d_out;

    static bool attr_set = false;
    if (!attr_set) {
        cudaFuncSetAttribute(kfused, cudaFuncAttributeMaxDynamicSharedMemorySize,
                             SM_FLTS * 4);
        attr_set = true;
    }
    kfused<<<256, 256, SM_FLTS * 4>>>(x, lw, lb, a, bias, out);
}